// round 1
// baseline (speedup 1.0000x reference)
#include <cuda_runtime.h>

#define D 3
#define HID 64
#define WIDTH 64
#define BATCH 500000
#define P_OUT (3 * D * WIDTH + WIDTH)   // 640
#define ROWS_PER_THREAD 4
#define NTHREADS_MAIN 256

// Hypernet output, AoS per hidden unit j: [w0,w1,w2,b][u0,u1,u2,wu]
__device__ float4 g_params[2 * WIDTH];

// ---------------------------------------------------------------------------
// Kernel 1: scalar hypernet. One block of 640 threads. Negligible cost.
// ---------------------------------------------------------------------------
__global__ void hypernet_kernel(const float* __restrict__ t,
                                const float* __restrict__ fc1_w,
                                const float* __restrict__ fc1_b,
                                const float* __restrict__ fc2_w,
                                const float* __restrict__ fc2_b,
                                const float* __restrict__ fc3_w,
                                const float* __restrict__ fc3_b) {
    __shared__ float h1[HID];
    __shared__ float h2[HID];
    __shared__ float p[P_OUT];
    __shared__ float Wsh[WIDTH * D];
    __shared__ float Ush[WIDTH * D];

    const int tid = threadIdx.x;

    // layer 1: p = tanh(t * fc1_w + fc1_b)
    if (tid < HID) {
        h1[tid] = tanhf(t[0] * fc1_w[tid] + fc1_b[tid]);
    }
    __syncthreads();

    // layer 2: h2 = tanh(fc2_w @ h1 + fc2_b)
    if (tid < HID) {
        float acc = fc2_b[tid];
#pragma unroll 8
        for (int k = 0; k < HID; k++) acc = fmaf(fc2_w[tid * HID + k], h1[k], acc);
        h2[tid] = tanhf(acc);
    }
    __syncthreads();

    // layer 3: p = fc3_w @ h2 + fc3_b   (640 outputs)
    if (tid < P_OUT) {
        float acc = fc3_b[tid];
#pragma unroll 8
        for (int k = 0; k < HID; k++) acc = fmaf(fc3_w[tid * HID + k], h2[k], acc);
        p[tid] = acc;
    }
    __syncthreads();

    // split: W = p[0:192], U = p[192:384] * sigmoid(p[384:576]), B = p[576:640]
    if (tid < WIDTH * D) {
        Wsh[tid] = p[tid];
        float g = p[2 * WIDTH * D + tid];
        float sg = 1.0f / (1.0f + __expf(-g));
        Ush[tid] = p[WIDTH * D + tid] * sg;
    }
    __syncthreads();

    if (tid < WIDTH) {
        const int j = tid;
        float w0 = Wsh[3 * j + 0], w1 = Wsh[3 * j + 1], w2 = Wsh[3 * j + 2];
        float u0 = Ush[3 * j + 0], u1 = Ush[3 * j + 1], u2 = Ush[3 * j + 2];
        float b  = p[3 * WIDTH * D + j];
        float wu = w0 * u0 + w1 * u1 + w2 * u2;
        g_params[2 * j + 0] = make_float4(w0, w1, w2, b);
        g_params[2 * j + 1] = make_float4(u0, u1, u2, wu);
    }
}

// ---------------------------------------------------------------------------
// tanh via 2 MUFU ops, numerically safe at both tails (no clamp needed):
//   e = exp(2a); r = 2/(e+1); h = 1-r; 1-h^2 = r*(2-r)   <- no cancellation
//   a -> +inf: e=inf, r=0, h=1, om=0.   a -> -inf: e=0, r=2, h=-1, om=0.
// ---------------------------------------------------------------------------
__device__ __forceinline__ void tanh_pair(float a, float& h, float& om) {
    float e = __expf(2.0f * a);
    float r = __fdividef(2.0f, e + 1.0f);
    h  = 1.0f - r;
    om = r * (2.0f - r);
}

// ---------------------------------------------------------------------------
// Kernel 2: batch map. 4 consecutive rows per thread -> all I/O is float4.
// Params broadcast from shared: 2 LDS.128 per hidden unit per 4 rows.
// ---------------------------------------------------------------------------
__global__ void __launch_bounds__(NTHREADS_MAIN)
cnf_kernel(const float* __restrict__ z, float* __restrict__ out) {
    __shared__ float4 sp[2 * WIDTH];

    const int tid = threadIdx.x;
    if (tid < 2 * WIDTH) sp[tid] = g_params[tid];
    __syncthreads();

    const int t = blockIdx.x * NTHREADS_MAIN + tid;
    if (t >= BATCH / ROWS_PER_THREAD) return;

    // 4 rows x 3 comps = 12 floats = 3 aligned float4 loads
    const float4* zp = reinterpret_cast<const float4*>(z) + (size_t)t * 3;
    float4 za = zp[0], zb = zp[1], zc = zp[2];
    const float z00 = za.x, z01 = za.y, z02 = za.z;
    const float z10 = za.w, z11 = zb.x, z12 = zb.y;
    const float z20 = zb.z, z21 = zb.w, z22 = zc.x;
    const float z30 = zc.y, z31 = zc.z, z32 = zc.w;

    float d00 = 0.f, d01 = 0.f, d02 = 0.f;
    float d10 = 0.f, d11 = 0.f, d12 = 0.f;
    float d20 = 0.f, d21 = 0.f, d22 = 0.f;
    float d30 = 0.f, d31 = 0.f, d32 = 0.f;
    float tr0 = 0.f, tr1 = 0.f, tr2 = 0.f, tr3 = 0.f;

#pragma unroll 4
    for (int j = 0; j < WIDTH; j++) {
        const float4 wb = sp[2 * j + 0];   // w0,w1,w2,b
        const float4 uw = sp[2 * j + 1];   // u0,u1,u2,wu

        float a0 = fmaf(wb.x, z00, fmaf(wb.y, z01, fmaf(wb.z, z02, wb.w)));
        float a1 = fmaf(wb.x, z10, fmaf(wb.y, z11, fmaf(wb.z, z12, wb.w)));
        float a2 = fmaf(wb.x, z20, fmaf(wb.y, z21, fmaf(wb.z, z22, wb.w)));
        float a3 = fmaf(wb.x, z30, fmaf(wb.y, z31, fmaf(wb.z, z32, wb.w)));

        float h0, o0, h1_, o1, h2_, o2, h3, o3;
        tanh_pair(a0, h0, o0);
        tanh_pair(a1, h1_, o1);
        tanh_pair(a2, h2_, o2);
        tanh_pair(a3, h3, o3);

        d00 = fmaf(h0, uw.x, d00); d01 = fmaf(h0, uw.y, d01); d02 = fmaf(h0, uw.z, d02);
        d10 = fmaf(h1_, uw.x, d10); d11 = fmaf(h1_, uw.y, d11); d12 = fmaf(h1_, uw.z, d12);
        d20 = fmaf(h2_, uw.x, d20); d21 = fmaf(h2_, uw.y, d21); d22 = fmaf(h2_, uw.z, d22);
        d30 = fmaf(h3, uw.x, d30); d31 = fmaf(h3, uw.y, d31); d32 = fmaf(h3, uw.z, d32);

        tr0 = fmaf(o0, uw.w, tr0);
        tr1 = fmaf(o1, uw.w, tr1);
        tr2 = fmaf(o2, uw.w, tr2);
        tr3 = fmaf(o3, uw.w, tr3);
    }

    const float inv = 1.0f / (float)WIDTH;

    // dz_dt: 12 contiguous floats at out[12*t]
    float4* dz = reinterpret_cast<float4*>(out) + (size_t)t * 3;
    dz[0] = make_float4(d00 * inv, d01 * inv, d02 * inv, d10 * inv);
    dz[1] = make_float4(d11 * inv, d12 * inv, d20 * inv, d21 * inv);
    dz[2] = make_float4(d22 * inv, d30 * inv, d31 * inv, d32 * inv);

    // dlogp_z_dt: 4 contiguous floats at out[3*BATCH + 4*t]
    float4* dl = reinterpret_cast<float4*>(out + (size_t)3 * BATCH) + t;
    *dl = make_float4(-tr0 * inv, -tr1 * inv, -tr2 * inv, -tr3 * inv);
}

// ---------------------------------------------------------------------------
extern "C" void kernel_launch(void* const* d_in, const int* in_sizes, int n_in,
                              void* d_out, int out_size) {
    const float* t     = (const float*)d_in[0];
    const float* z     = (const float*)d_in[1];
    // d_in[2] = logp_z (unused: dlogp/dt does not depend on it)
    const float* fc1_w = (const float*)d_in[3];
    const float* fc1_b = (const float*)d_in[4];
    const float* fc2_w = (const float*)d_in[5];
    const float* fc2_b = (const float*)d_in[6];
    const float* fc3_w = (const float*)d_in[7];
    const float* fc3_b = (const float*)d_in[8];
    float* out = (float*)d_out;

    hypernet_kernel<<<1, P_OUT>>>(t, fc1_w, fc1_b, fc2_w, fc2_b, fc3_w, fc3_b);

    const int nthreads_total = BATCH / ROWS_PER_THREAD;           // 125000
    const int nblocks = (nthreads_total + NTHREADS_MAIN - 1) / NTHREADS_MAIN;  // 489
    cnf_kernel<<<nblocks, NTHREADS_MAIN>>>(z, out);
}

// round 13
// speedup vs baseline: 2.1281x; 2.1281x over previous
#include <cuda_runtime.h>

#define D 3
#define HID 64
#define WIDTH 64
#define BATCH 500000
#define BLOCK_P (D * WIDTH)             // 192
#define P_OUT (3 * BLOCK_P + WIDTH)     // 640
#define ROWS_PER_THREAD 4
#define NTHREADS_MAIN 256
#define HYPER_BLOCKS 20                 // 20 * 32 rows = 640

// Raw hypernet output p[640] (W | U_raw | G | B)
__device__ float g_p[P_OUT];

// ---------------------------------------------------------------------------
// f32x2 packed-math helpers (sm_103a FFMA2 path)
// ---------------------------------------------------------------------------
__device__ __forceinline__ unsigned long long pack2(float lo, float hi) {
    unsigned long long r;
    asm("mov.b64 %0, {%1, %2};" : "=l"(r) : "f"(lo), "f"(hi));
    return r;
}
__device__ __forceinline__ void unpack2(unsigned long long v, float& lo, float& hi) {
    asm("mov.b64 {%0, %1}, %2;" : "=f"(lo), "=f"(hi) : "l"(v));
}
__device__ __forceinline__ unsigned long long fma2(unsigned long long a,
                                                   unsigned long long b,
                                                   unsigned long long c) {
    unsigned long long d;
    asm("fma.rn.f32x2 %0, %1, %2, %3;" : "=l"(d) : "l"(a), "l"(b), "l"(c));
    return d;
}
__device__ __forceinline__ float tanh_apx(float x) {
    float y;
    asm("tanh.approx.f32 %0, %1;" : "=f"(y) : "f"(x));
    return y;
}

// ---------------------------------------------------------------------------
// Kernel 1: hypernet, parallel + coalesced. 20 blocks x 256 threads.
// Layers 1-2 computed redundantly per block (cheap, coalesced, warp-per-row);
// layer 3: block b owns output rows [b*32, b*32+32), warp-per-row.
// ---------------------------------------------------------------------------
__global__ void __launch_bounds__(256)
hypernet_kernel(const float* __restrict__ t,
                const float* __restrict__ fc1_w,
                const float* __restrict__ fc1_b,
                const float* __restrict__ fc2_w,
                const float* __restrict__ fc2_b,
                const float* __restrict__ fc3_w,
                const float* __restrict__ fc3_b) {
    __shared__ float h1[HID];
    __shared__ float h2[HID];

    const int tid  = threadIdx.x;
    const int warp = tid >> 5;
    const int lane = tid & 31;

    // layer 1
    if (tid < HID) h1[tid] = tanhf(t[0] * fc1_w[tid] + fc1_b[tid]);
    __syncthreads();

    // layer 2: warp-per-row, coalesced fc2_w reads, shuffle reduce
    for (int r = warp; r < HID; r += 8) {
        float acc = fc2_w[r * HID + lane] * h1[lane]
                  + fc2_w[r * HID + lane + 32] * h1[lane + 32];
#pragma unroll
        for (int off = 16; off; off >>= 1) acc += __shfl_xor_sync(0xffffffffu, acc, off);
        if (lane == 0) h2[r] = tanhf(acc + fc2_b[r]);
    }
    __syncthreads();

    // layer 3: 32 rows for this block, warp-per-row (4 rows per warp)
    const int row0 = blockIdx.x * 32;
#pragma unroll
    for (int i = 0; i < 4; i++) {
        int r = row0 + warp + i * 8;
        float acc = fc3_w[r * HID + lane] * h2[lane]
                  + fc3_w[r * HID + lane + 32] * h2[lane + 32];
#pragma unroll
        for (int off = 16; off; off >>= 1) acc += __shfl_xor_sync(0xffffffffu, acc, off);
        if (lane == 0) g_p[r] = acc + fc3_b[r];
    }
}

// ---------------------------------------------------------------------------
// Kernel 2: batch map. Rows paired into f32x2; params pre-duplicated in
// shared as float2 so LDS.64 yields packed broadcast operands directly.
// Per hidden unit j per thread (4 rows): 16 FFMA2 + 4 MUFU.TANH + 8 LDS.64.
// ---------------------------------------------------------------------------
__global__ void __launch_bounds__(NTHREADS_MAIN)
cnf_kernel(const float* __restrict__ z, float* __restrict__ out) {
    // per j: {w0,w0}{w1,w1}{w2,w2}{b,b}{u0,u0}{u1,u1}{u2,u2}{wu,wu}
    __shared__ float2 spd[WIDTH * 8];

    const int tid = threadIdx.x;

    // Combine stage: thread j (< 64) builds duplicated params from raw p.
    if (tid < WIDTH) {
        const int j = tid;
        float w0 = g_p[3 * j + 0], w1 = g_p[3 * j + 1], w2 = g_p[3 * j + 2];
        float ur0 = g_p[BLOCK_P + 3 * j + 0];
        float ur1 = g_p[BLOCK_P + 3 * j + 1];
        float ur2 = g_p[BLOCK_P + 3 * j + 2];
        float gg0 = g_p[2 * BLOCK_P + 3 * j + 0];
        float gg1 = g_p[2 * BLOCK_P + 3 * j + 1];
        float gg2 = g_p[2 * BLOCK_P + 3 * j + 2];
        float b   = g_p[3 * BLOCK_P + j];
        float u0 = ur0 / (1.0f + __expf(-gg0));
        float u1 = ur1 / (1.0f + __expf(-gg1));
        float u2 = ur2 / (1.0f + __expf(-gg2));
        float wu = w0 * u0 + w1 * u1 + w2 * u2;
        spd[j * 8 + 0] = make_float2(w0, w0);
        spd[j * 8 + 1] = make_float2(w1, w1);
        spd[j * 8 + 2] = make_float2(w2, w2);
        spd[j * 8 + 3] = make_float2(b, b);
        spd[j * 8 + 4] = make_float2(u0, u0);
        spd[j * 8 + 5] = make_float2(u1, u1);
        spd[j * 8 + 6] = make_float2(u2, u2);
        spd[j * 8 + 7] = make_float2(wu, wu);
    }
    __syncthreads();

    const int t = blockIdx.x * NTHREADS_MAIN + tid;
    if (t >= BATCH / ROWS_PER_THREAD) return;

    // 4 rows x 3 comps = 3 aligned float4 loads
    const float4* zp = reinterpret_cast<const float4*>(z) + (size_t)t * 3;
    float4 za = zp[0], zb = zp[1], zc = zp[2];
    // rows: r0=(za.x,za.y,za.z) r1=(za.w,zb.x,zb.y) r2=(zb.z,zb.w,zc.x) r3=(zc.y,zc.z,zc.w)
    const unsigned long long zx01 = pack2(za.x, za.w);
    const unsigned long long zy01 = pack2(za.y, zb.x);
    const unsigned long long zz01 = pack2(za.z, zb.y);
    const unsigned long long zx23 = pack2(zb.z, zc.y);
    const unsigned long long zy23 = pack2(zb.w, zc.z);
    const unsigned long long zz23 = pack2(zc.x, zc.w);

    const unsigned long long m1 = pack2(-1.0f, -1.0f);

    unsigned long long dx01 = 0, dy01 = 0, dz01 = 0, tr01 = 0;
    unsigned long long dx23 = 0, dy23 = 0, dz23 = 0, tr23 = 0;

    const unsigned long long* sp = reinterpret_cast<const unsigned long long*>(spd);

#pragma unroll 8
    for (int j = 0; j < WIDTH; j++) {
        const unsigned long long* spj = sp + j * 8;
        const unsigned long long w0 = spj[0];
        const unsigned long long w1 = spj[1];
        const unsigned long long w2 = spj[2];
        const unsigned long long bb = spj[3];
        const unsigned long long u0 = spj[4];
        const unsigned long long u1 = spj[5];
        const unsigned long long u2 = spj[6];
        const unsigned long long wu = spj[7];

        unsigned long long a01 = fma2(w0, zx01, fma2(w1, zy01, fma2(w2, zz01, bb)));
        unsigned long long a23 = fma2(w0, zx23, fma2(w1, zy23, fma2(w2, zz23, bb)));

        float a0, a1, a2, a3;
        unpack2(a01, a0, a1);
        unpack2(a23, a2, a3);
        const unsigned long long h01 = pack2(tanh_apx(a0), tanh_apx(a1));
        const unsigned long long h23 = pack2(tanh_apx(a2), tanh_apx(a3));

        const unsigned long long hh01 = fma2(h01, h01, m1);   // h^2 - 1
        const unsigned long long hh23 = fma2(h23, h23, m1);

        dx01 = fma2(h01, u0, dx01);
        dy01 = fma2(h01, u1, dy01);
        dz01 = fma2(h01, u2, dz01);
        tr01 = fma2(hh01, wu, tr01);

        dx23 = fma2(h23, u0, dx23);
        dy23 = fma2(h23, u1, dy23);
        dz23 = fma2(h23, u2, dz23);
        tr23 = fma2(hh23, wu, tr23);
    }

    const float inv = 1.0f / (float)WIDTH;

    float x0, x1, x2, x3, y0, y1, y2, y3, q0, q1, q2, q3, t0, t1, t2, t3;
    unpack2(dx01, x0, x1); unpack2(dx23, x2, x3);
    unpack2(dy01, y0, y1); unpack2(dy23, y2, y3);
    unpack2(dz01, q0, q1); unpack2(dz23, q2, q3);
    unpack2(tr01, t0, t1); unpack2(tr23, t2, t3);

    // dz_dt: 12 contiguous floats at out[12*t]
    float4* dzp = reinterpret_cast<float4*>(out) + (size_t)t * 3;
    dzp[0] = make_float4(x0 * inv, y0 * inv, q0 * inv, x1 * inv);
    dzp[1] = make_float4(y1 * inv, q1 * inv, x2 * inv, y2 * inv);
    dzp[2] = make_float4(q2 * inv, x3 * inv, y3 * inv, q3 * inv);

    // dlogp_z_dt = sum((h^2-1)*wu)/WIDTH  (sign already folded)
    float4* dl = reinterpret_cast<float4*>(out + (size_t)3 * BATCH) + t;
    *dl = make_float4(t0 * inv, t1 * inv, t2 * inv, t3 * inv);
}

// ---------------------------------------------------------------------------
extern "C" void kernel_launch(void* const* d_in, const int* in_sizes, int n_in,
                              void* d_out, int out_size) {
    const float* t     = (const float*)d_in[0];
    const float* z     = (const float*)d_in[1];
    // d_in[2] = logp_z (unused)
    const float* fc1_w = (const float*)d_in[3];
    const float* fc1_b = (const float*)d_in[4];
    const float* fc2_w = (const float*)d_in[5];
    const float* fc2_b = (const float*)d_in[6];
    const float* fc3_w = (const float*)d_in[7];
    const float* fc3_b = (const float*)d_in[8];
    float* out = (float*)d_out;

    hypernet_kernel<<<HYPER_BLOCKS, 256>>>(t, fc1_w, fc1_b, fc2_w, fc2_b, fc3_w, fc3_b);

    const int nthreads_total = BATCH / ROWS_PER_THREAD;                        // 125000
    const int nblocks = (nthreads_total + NTHREADS_MAIN - 1) / NTHREADS_MAIN;  // 489
    cnf_kernel<<<nblocks, NTHREADS_MAIN>>>(z, out);
}